// round 17
// baseline (speedup 1.0000x reference)
#include <cuda_runtime.h>
#include <cstddef>

// ---------------------------------------------------------------------------
// StockPredictor: 2-layer LSTM (B=256, T=2048, D=1, H1=128, H2=64) + FC head.
// R17: 64 producers + 64 consumers, BOTH at 512 threads (16 warps/SM for
// latency hiding), 4 batches each, audited to fit the 128-reg cap w/o spill.
//   Producer: 1 row/thread; W_hh1 64 smem cols (pitch 68) + 64 reg floats.
//   Consumer: 2 parts x 256 rows over concat K=192 (part p: [96p,96p+96));
//             48 reg + 48 smem floats; partial sums via smem; activation
//             fused into 256 update threads; 3 barriers/step.
// Per-producer flags, release/acquire, end handshake resets for graph replay.
// ---------------------------------------------------------------------------

constexpr int T  = 2048;
constexpr int B  = 256;
constexpr int H1 = 128;
constexpr int G1 = 512;
constexpr int H2 = 64;
constexpr int G2 = 256;
constexpr int NP = 64;
constexpr int NC = 64;
constexpr int BBP = 4;

// Producer smem (floats)
constexpr int P_PITCH = 68;                 // 17*16B odd -> conflict-free
constexpr int P_WS  = 0;                    // [512][68]
constexpr int P_XS  = G1 * P_PITCH;         // 34816  [4][2048]
constexpr int P_HS  = P_XS + BBP * T;       // 43008  [4][128]
constexpr int P_GS  = P_HS + BBP * H1;      // 43520  [4][512]
constexpr int P_END = P_GS + BBP * G1;      // 45568 floats = 182272 B

// Consumer smem (floats)
constexpr int C_PITCH = 52;                 // 13*16B odd -> conflict-free
constexpr int C_WS  = 0;                    // [512][52]  (part,row) weight rows
constexpr int C_HC  = 512 * C_PITCH;        // 26624  hcat[4][192]
constexpr int C_PS  = C_HC + BBP * 192;     // 27392  ps[2][4][256]
constexpr int C_BS  = C_PS + 2 * BBP * G2;  // 29440  [256]
constexpr int C_ST  = C_BS + G2;            // 29696  [4][32]

constexpr size_t SMEM_MAX = (size_t)P_END * sizeof(float);  // 182272

__device__ float g_h1seq[(size_t)B * T * H1];
__device__ int   g_flag[NP];
__device__ int   g_done[NC];

// ---------------------------------------------------------------------------
__device__ __forceinline__ void fma2(unsigned long long& acc,
                                     unsigned long long a,
                                     unsigned long long b) {
    asm("fma.rn.f32x2 %0, %1, %2, %0;" : "+l"(acc) : "l"(a), "l"(b));
}
__device__ __forceinline__ float f32x2_sum2(unsigned long long u,
                                            unsigned long long v) {
    unsigned long long s;
    asm("add.rn.f32x2 %0, %1, %2;" : "=l"(s) : "l"(u), "l"(v));
    float lo, hi;
    asm("mov.b64 {%0, %1}, %2;" : "=f"(lo), "=f"(hi) : "l"(s));
    return lo + hi;
}
__device__ __forceinline__ float sigmoid_fast(float x) {
    return __fdividef(1.0f, 1.0f + __expf(-x));
}
__device__ __forceinline__ float tanh_acc(float x) {
    return fmaf(2.0f, sigmoid_fast(2.0f * x), -1.0f);
}
__device__ __forceinline__ int ld_acquire(const int* p) {
    int v;
    asm volatile("ld.acquire.gpu.global.b32 %0, [%1];" : "=r"(v) : "l"(p) : "memory");
    return v;
}
__device__ __forceinline__ void st_release(int* p, int v) {
    asm volatile("st.release.gpu.global.b32 [%0], %1;" :: "l"(p), "r"(v) : "memory");
}

// 1 weight row x 4 batch h streams (8 fma2 / iter)
template <int N>
__device__ __forceinline__ void dot4(const ulonglong2* __restrict__ w,
                                     const float* h0, const float* h1,
                                     const float* h2, const float* h3,
                                     unsigned long long* acc /*[8]*/)
{
    const ulonglong2* p0 = reinterpret_cast<const ulonglong2*>(h0);
    const ulonglong2* p1 = reinterpret_cast<const ulonglong2*>(h1);
    const ulonglong2* p2 = reinterpret_cast<const ulonglong2*>(h2);
    const ulonglong2* p3 = reinterpret_cast<const ulonglong2*>(h3);
    #pragma unroll
    for (int i = 0; i < N; i++) {
        ulonglong2 wv = w[i];
        ulonglong2 q0 = p0[i], q1 = p1[i], q2 = p2[i], q3 = p3[i];
        fma2(acc[0], wv.x, q0.x); fma2(acc[1], wv.y, q0.y);
        fma2(acc[2], wv.x, q1.x); fma2(acc[3], wv.y, q1.y);
        fma2(acc[4], wv.x, q2.x); fma2(acc[5], wv.y, q2.y);
        fma2(acc[6], wv.x, q3.x); fma2(acc[7], wv.y, q3.y);
    }
}

// ---------------------------------------------------------------------------
__global__ __launch_bounds__(512, 1)
void fused_lstm_kernel(const float* __restrict__ x,
                       const float* __restrict__ W_ih1,
                       const float* __restrict__ W_hh1,
                       const float* __restrict__ b_ih1,
                       const float* __restrict__ b_hh1,
                       const float* __restrict__ W_ih2,
                       const float* __restrict__ W_hh2,
                       const float* __restrict__ b_ih2,
                       const float* __restrict__ b_hh2,
                       const float* __restrict__ W_fc1,
                       const float* __restrict__ b_fc1,
                       const float* __restrict__ W_fc2,
                       const float* __restrict__ b_fc2,
                       float* __restrict__ out)
{
    extern __shared__ float sm[];
    const int tid = threadIdx.x;

    if (blockIdx.x < NP) {
        // ================= PRODUCER: layer 1, 4 batches, 512 thr ============
        const int pb = blockIdx.x;
        const int bg = pb * BBP;
        float* Ws = sm + P_WS;
        float* xs = sm + P_XS;
        float* hs = sm + P_HS;     // [4][128]
        float* gs = sm + P_GS;     // [4][512]

        const int r = tid;         // gate row 0..511

        // smem weights: cols [0,64) of every row
        for (int i = tid; i < G1 * 64; i += 512) {
            int rr = i >> 6, c = i & 63;
            Ws[rr * P_PITCH + c] = W_hh1[rr * H1 + c];
        }
        // reg weights: cols [64,128) of row r = 16 u2 = 64 regs
        ulonglong2 wr[16];
        {
            const ulonglong2* s = reinterpret_cast<const ulonglong2*>(W_hh1 + r * H1 + 64);
            #pragma unroll
            for (int j = 0; j < 16; j++) wr[j] = s[j];
        }
        const float wx   = W_ih1[r];
        const float bias = b_ih1[r] + b_hh1[r];

        for (int i = tid; i < BBP * T; i += 512)
            xs[i] = x[(size_t)bg * T + i];
        hs[tid & 511] = 0.0f;      // 512 slots, one per thread
        __syncthreads();

        float cst = 0.0f;          // update slot tid: bb = tid>>7, m = tid&127
        const int ub = tid >> 7;
        const int um = tid & (H1 - 1);
        const bool is_g = (r >= 256) && (r < 384);   // warps 8-11, uniform

        const ulonglong2* ws = reinterpret_cast<const ulonglong2*>(Ws + r * P_PITCH);

        for (int t = 0; t < T; t++) {
            unsigned long long acc[8];
            #pragma unroll
            for (int j = 0; j < 8; j++) acc[j] = 0ull;

            dot4<16>(ws, hs, hs + 128, hs + 256, hs + 384, acc);              // k [0,64)
            dot4<16>(wr, hs + 64, hs + 192, hs + 320, hs + 448, acc);         // k [64,128)

            #pragma unroll
            for (int bb = 0; bb < BBP; bb++) {
                float v = fmaf(xs[bb * T + t], wx, bias)
                          + f32x2_sum2(acc[2 * bb], acc[2 * bb + 1]);
                gs[bb * G1 + r] = is_g ? tanh_acc(v) : sigmoid_fast(v);
            }
            __syncthreads();

            // update: exactly one slot per thread (512 slots = 4b x 128)
            {
                const float* gb = gs + ub * G1;
                float i_ = gb[um], f_ = gb[H1 + um], g_ = gb[2 * H1 + um], o_ = gb[3 * H1 + um];
                cst = fmaf(f_, cst, i_ * g_);
                float h = o_ * tanh_acc(cst);
                hs[tid] = h;
                g_h1seq[((size_t)(bg + ub) * T + t) * H1 + um] = h;
            }
            __syncthreads();
            if (tid == 0) st_release(&g_flag[pb], t + 1);
        }

        if (tid == 0) {
            while (ld_acquire(&g_done[pb]) == 0) { __nanosleep(128); }
            g_flag[pb] = 0;
            g_done[pb] = 0;
        }
    } else {
        // ================= CONSUMER: layer 2 + FC, 4 batches, 512 thr =======
        const int cb = blockIdx.x - NP;
        const int bg = cb * BBP;
        float* Ws2   = sm + C_WS;    // [512][C_PITCH]
        float* hcat  = sm + C_HC;    // [4][192] = h1 | h2
        float* ps    = sm + C_PS;    // [2][4][256] partials
        float* bsm   = sm + C_BS;    // [256]
        float* stage = sm + C_ST;    // [4][32]

        const int r    = tid & 255;
        const int part = tid >> 8;        // 0 or 1
        const int koff = part * 96;

        // reg weights: concat [koff, koff+48) = 12 u2 = 48 regs
        //   part0: W_ih2[r][0:48)
        //   part1: W_ih2[r][96:128) + W_hh2[r][0:16)
        ulonglong2 wr[12];
        if (part == 0) {
            const ulonglong2* s = reinterpret_cast<const ulonglong2*>(W_ih2 + r * H1);
            #pragma unroll
            for (int j = 0; j < 12; j++) wr[j] = s[j];
        } else {
            const ulonglong2* sa = reinterpret_cast<const ulonglong2*>(W_ih2 + r * H1 + 96);
            const ulonglong2* sb = reinterpret_cast<const ulonglong2*>(W_hh2 + r * H2);
            #pragma unroll
            for (int j = 0; j < 8; j++) wr[j] = sa[j];
            #pragma unroll
            for (int j = 0; j < 4; j++) wr[8 + j] = sb[j];
        }
        // smem weights: concat [koff+48, koff+96) = 48 floats, row tid
        //   part0: W_ih2[r][48:96)   part1: W_hh2[r][16:64)
        {
            float* wrow = Ws2 + tid * C_PITCH;
            const float* src = (part == 0) ? (W_ih2 + r * H1 + 48)
                                           : (W_hh2 + r * H2 + 16);
            #pragma unroll
            for (int j = 0; j < 48; j += 4)
                *reinterpret_cast<float4*>(wrow + j) =
                    *reinterpret_cast<const float4*>(src + j);
        }
        if (tid < G2) bsm[tid] = b_ih2[tid] + b_hh2[tid];
        for (int i = tid; i < BBP * 192; i += 512) hcat[i] = 0.0f;
        __syncthreads();

        float cst = 0.0f;                 // update slot (tid<256): bb=tid>>6, m=tid&63
        const int ub = tid >> 6;
        const int um = tid & (H2 - 1);
        const ulonglong2* ws = reinterpret_cast<const ulonglong2*>(Ws2 + tid * C_PITCH);
        const int sbb = tid >> 7;         // staging slot: bb = tid>>7, mm = tid&127
        const int smm = tid & (H1 - 1);

        for (int t = 0; t < T; t++) {
            if (tid == 0) {
                while (ld_acquire(&g_flag[cb]) < t + 1) { __nanosleep(32); }
            }
            __syncthreads();   // bar1: flag verified; also orders prev update

            // stage h1(t): one slot per thread (512 = 4b x 128)
            hcat[sbb * 192 + smm] =
                __ldcg(&g_h1seq[((size_t)(bg + sbb) * T + t) * H1 + smm]);
            __syncthreads();   // bar2: h1 staged

            unsigned long long acc[8];
            #pragma unroll
            for (int j = 0; j < 8; j++) acc[j] = 0ull;
            dot4<12>(wr, hcat + koff,      hcat + 192 + koff,
                         hcat + 384 + koff, hcat + 576 + koff, acc);           // reg w
            dot4<12>(ws, hcat + koff + 48,  hcat + 192 + koff + 48,
                         hcat + 384 + koff + 48, hcat + 576 + koff + 48, acc); // smem w

            #pragma unroll
            for (int bb = 0; bb < BBP; bb++)
                ps[part * 1024 + bb * 256 + r] = f32x2_sum2(acc[2 * bb], acc[2 * bb + 1]);
            __syncthreads();   // bar3: partials ready

            // update (tid<256): combine parts, activate, update c/h2
            if (tid < BBP * H2) {
                float gate[4];
                #pragma unroll
                for (int gidx = 0; gidx < 4; gidx++) {
                    int row = gidx * H2 + um;
                    gate[gidx] = bsm[row]
                               + ps[ub * 256 + row]
                               + ps[1024 + ub * 256 + row];
                }
                float i_ = sigmoid_fast(gate[0]);
                float f_ = sigmoid_fast(gate[1]);
                float g_ = tanh_acc(gate[2]);
                float o_ = sigmoid_fast(gate[3]);
                cst = fmaf(f_, cst, i_ * g_);
                hcat[ub * 192 + H1 + um] = o_ * tanh_acc(cst);
            }
            // no end barrier: bar1+bar2 of next iteration order hcat/ps reuse
        }
        __syncthreads();       // final: h2 complete before FC head

        // ---- FC head on final h2 (unroll-limited; cold code) ----
        if (tid < BBP * 25) {
            int bb = tid / 25;
            int i  = tid - bb * 25;
            float a = b_fc1[i];
            #pragma unroll 4
            for (int k = 0; k < H2; k++)
                a = fmaf(W_fc1[i * H2 + k], hcat[bb * 192 + H1 + k], a);
            stage[bb * 32 + i] = a;
        }
        __syncthreads();
        if (tid < BBP) {
            float a = b_fc2[0];
            #pragma unroll 5
            for (int i = 0; i < 25; i++)
                a = fmaf(W_fc2[i], stage[tid * 32 + i], a);
            out[bg + tid] = a;
        }
        if (tid == 0) st_release(&g_done[cb], 1);
    }
}

// ---------------------------------------------------------------------------
extern "C" void kernel_launch(void* const* d_in, const int* in_sizes, int n_in,
                              void* d_out, int out_size)
{
    const float* x     = (const float*)d_in[0];
    const float* W_ih1 = (const float*)d_in[1];
    const float* W_hh1 = (const float*)d_in[2];
    const float* b_ih1 = (const float*)d_in[3];
    const float* b_hh1 = (const float*)d_in[4];
    const float* W_ih2 = (const float*)d_in[5];
    const float* W_hh2 = (const float*)d_in[6];
    const float* b_ih2 = (const float*)d_in[7];
    const float* b_hh2 = (const float*)d_in[8];
    const float* W_fc1 = (const float*)d_in[9];
    const float* b_fc1 = (const float*)d_in[10];
    const float* W_fc2 = (const float*)d_in[11];
    const float* b_fc2 = (const float*)d_in[12];
    float* out = (float*)d_out;

    static bool attr_done = false;
    if (!attr_done) {
        cudaFuncSetAttribute(fused_lstm_kernel,
                             cudaFuncAttributeMaxDynamicSharedMemorySize, (int)SMEM_MAX);
        attr_done = true;
    }

    fused_lstm_kernel<<<NP + NC, 512, SMEM_MAX>>>(
        x, W_ih1, W_hh1, b_ih1, b_hh1,
        W_ih2, W_hh2, b_ih2, b_hh2,
        W_fc1, b_fc1, W_fc2, b_fc2, out);
}